// round 5
// baseline (speedup 1.0000x reference)
#include <cuda_runtime.h>
#include <cstdint>
#include <cstddef>

// Problem dims
#define B_  512
#define S_  1024
#define I_  64
#define H_  128
#define G_  384   // 3*H
#define C_  10

// Scratch (device globals: allocation APIs are forbidden)
__device__ float g_xg[(size_t)B_ * S_ * G_];    // input-gate preactivations
__device__ float g_h1[(size_t)B_ * S_ * H_];    // layer0 hidden outputs
__device__ float g_h2last[B_ * H_];             // last hidden of layer1

typedef unsigned long long u64;

__device__ __forceinline__ u64 pk2(float lo, float hi) {
    u64 r; asm("mov.b64 %0, {%1, %2};" : "=l"(r) : "f"(lo), "f"(hi)); return r;
}
__device__ __forceinline__ void upk2(u64 v, float& lo, float& hi) {
    asm("mov.b64 {%0, %1}, %2;" : "=f"(lo), "=f"(hi) : "l"(v));
}
__device__ __forceinline__ void fma2(u64& d, u64 a, u64 b) {
    asm("fma.rn.f32x2 %0, %1, %2, %0;" : "+l"(d) : "l"(a), "l"(b));
}

// MUFU.TANH — single-op tanh (sm_75+), ~2^-11 rel err
__device__ __forceinline__ float tanh_ap(float x) {
    float y; asm("tanh.approx.f32 %0, %1;" : "=f"(y) : "f"(x)); return y;
}
__device__ __forceinline__ float sig_ap(float x) {
    return fmaf(tanh_ap(0.5f * x), 0.5f, 0.5f);
}

// ============================================================================
// Phase 1/3: xg[m][g] = sum_k A[m][k] * W[g][k] + bias[g]
// Persistent CTAs; W k-major in smem; 64-row M tiles; fp32x2 FMA.
// 512 threads (16 warps, 4/SMSP), 4 rows/warp. Next A tile prefetched in regs.
// ============================================================================
template<int K, bool A_IS_H1>
__global__ __launch_bounds__(512) void gemm_xg_kernel(
    const float* __restrict__ Ain, const float* __restrict__ W,
    const float* __restrict__ bias, int ntiles)
{
    extern __shared__ float smem[];
    float* Ws = smem;              // [K][384], k-major
    float* As = smem + K * G_;     // [64][K]
    const float* A = A_IS_H1 ? g_h1 : Ain;

    const int tid = threadIdx.x;
    constexpr int PF = (64 * K / 4) / 512;   // float4 per thread per tile (2 or 4)

    for (int idx = tid; idx < G_ * (K / 4); idx += 512) {
        int kq = idx / G_;
        int g  = idx - kq * G_;
        float4 w4 = *reinterpret_cast<const float4*>(W + (size_t)g * K + 4 * kq);
        Ws[(4 * kq + 0) * G_ + g] = w4.x;
        Ws[(4 * kq + 1) * G_ + g] = w4.y;
        Ws[(4 * kq + 2) * G_ + g] = w4.z;
        Ws[(4 * kq + 3) * G_ + g] = w4.w;
    }

    const int cg = tid & 31;
    const int rg = tid >> 5;       // 0..15, rows rg*4 .. rg*4+3

    float4 bv[3];
#pragma unroll
    for (int gg = 0; gg < 3; ++gg)
        bv[gg] = *reinterpret_cast<const float4*>(bias + gg * H_ + 4 * cg);

    int tile = blockIdx.x;
    float4 pf[PF];
    if (tile < ntiles) {
        const float4* Ab = reinterpret_cast<const float4*>(A + (size_t)tile * 64 * K);
#pragma unroll
        for (int i = 0; i < PF; ++i) pf[i] = Ab[tid + 512 * i];
    }
    __syncthreads();

    for (; tile < ntiles; tile += gridDim.x) {
#pragma unroll
        for (int i = 0; i < PF; ++i)
            reinterpret_cast<float4*>(As)[tid + 512 * i] = pf[i];
        __syncthreads();

        int ntile = tile + gridDim.x;
        if (ntile < ntiles) {
            const float4* Ab = reinterpret_cast<const float4*>(A + (size_t)ntile * 64 * K);
#pragma unroll
            for (int i = 0; i < PF; ++i) pf[i] = Ab[tid + 512 * i];
        }

        u64 acc[4][3][2];
#pragma unroll
        for (int r = 0; r < 4; ++r)
#pragma unroll
            for (int gg = 0; gg < 3; ++gg) {
                acc[r][gg][0] = 0ull;
                acc[r][gg][1] = 0ull;
            }

#pragma unroll 2
        for (int k4 = 0; k4 < K; k4 += 4) {
            float4 af[4];
#pragma unroll
            for (int r = 0; r < 4; ++r)
                af[r] = *reinterpret_cast<const float4*>(&As[(rg * 4 + r) * K + k4]);
#pragma unroll
            for (int kk = 0; kk < 4; ++kk) {
                ulonglong2 wp[3];
#pragma unroll
                for (int gg = 0; gg < 3; ++gg)
                    wp[gg] = *reinterpret_cast<const ulonglong2*>(
                        &Ws[(size_t)(k4 + kk) * G_ + gg * H_ + 4 * cg]);
#pragma unroll
                for (int r = 0; r < 4; ++r) {
                    float a = (kk == 0) ? af[r].x : (kk == 1) ? af[r].y
                            : (kk == 2) ? af[r].z : af[r].w;
                    u64 ad = pk2(a, a);
#pragma unroll
                    for (int gg = 0; gg < 3; ++gg) {
                        fma2(acc[r][gg][0], ad, wp[gg].x);
                        fma2(acc[r][gg][1], ad, wp[gg].y);
                    }
                }
            }
        }

        float* Cb = g_xg + (size_t)tile * 64 * G_;
#pragma unroll
        for (int r = 0; r < 4; ++r) {
#pragma unroll
            for (int gg = 0; gg < 3; ++gg) {
                float x0, x1, x2, x3;
                upk2(acc[r][gg][0], x0, x1);
                upk2(acc[r][gg][1], x2, x3);
                float4 o = make_float4(x0 + bv[gg].x, x1 + bv[gg].y,
                                       x2 + bv[gg].z, x3 + bv[gg].w);
                *reinterpret_cast<float4*>(&Cb[(size_t)(rg * 4 + r) * G_ + gg * H_ + 4 * cg]) = o;
            }
        }
        __syncthreads();
    }
}

// ============================================================================
// Phase 2/4: recurrent scan, split-k x2. 128 CTAs x 4 batch rows, 768 threads.
// lo threads (0..383): gate g=tid, k in [0,64); hi threads: gate g=tid-384,
// k in [64,128). 64 w-regs/thread -> 6 warps/SMSP for latency hiding.
// Partial dots exchanged via smem (each side writes only what the other needs).
// Phase A: gate nonlinearities, 2 rows/thread over all 768 threads.
// Phase B: tanh+blend, 512 elements over threads 0..511.
// ============================================================================
template<bool WRITE_ALL>
__global__ __launch_bounds__(768, 1) void gru_rec_kernel(
    const float* __restrict__ Whh, const float* __restrict__ bhh)
{
    __shared__ float  h_s[4][H_];      // h state, row-planar
    __shared__ float2 rz[4][H_];       // .x = sigma(r), .y = sigma(z)
    __shared__ float2 gx[4][H_];       // .x = raw n-preact, .y = xn
    __shared__ float2 partL[G_];       // lo's partials for rows 2,3 (hi reads)
    __shared__ float2 partH[G_];       // hi's partials for rows 0,1 (lo reads)

    const int tid = threadIdx.x;
    const bool hi = (tid >= G_);
    const int g   = hi ? tid - G_ : tid;
    const int rb  = blockIdx.x * 4;
    const int koff = hi ? (H_ / 2) : 0;

    // Half of W_hh row: 32 packed (w[2k],w[2k+1]) u64s — loop-invariant regs
    u64 wp[32];
    const u64* wrow = reinterpret_cast<const u64*>(Whh + (size_t)g * H_ + koff);
#pragma unroll
    for (int kk = 0; kk < 32; ++kk) wp[kk] = wrow[kk];
    const float bh = bhh[g];

    for (int idx = tid; idx < 4 * H_; idx += 768)
        (&h_s[0][0])[idx] = 0.f;
    __syncthreads();

    const int sec  = g >> 7;
    const int j    = g & 127;
    const int rowA = hi ? 2 : 0;       // phase-A rows: rowA, rowA+1

    const size_t rstride = (size_t)S_ * G_;
    const float* xp = g_xg + (size_t)(rb + rowA) * rstride + g;

    // phase-B assignment: element tid (active if < 512)
    const int rB = tid >> 7;
    const int cB = tid & 127;
    float* houtB = g_h1 + ((size_t)(rb + rB) * S_) * H_ + cB;

    const ulonglong2* hp0 = reinterpret_cast<const ulonglong2*>(&h_s[0][koff]);
    const ulonglong2* hp1 = reinterpret_cast<const ulonglong2*>(&h_s[1][koff]);
    const ulonglong2* hp2 = reinterpret_cast<const ulonglong2*>(&h_s[2][koff]);
    const ulonglong2* hp3 = reinterpret_cast<const ulonglong2*>(&h_s[3][koff]);

    for (int t = 0; t < S_; ++t) {
        // xg loads for this thread's 2 phase-A rows (consumed after the dot)
        float xva = __ldg(xp);
        float xvb = __ldg(xp + rstride);
        xp += G_;

        // -------- half-dot: h(t-1)[koff..koff+64) . w  for 4 rows --------
        u64 a0 = 0ull, a1 = 0ull, a2 = 0ull, a3 = 0ull;
#pragma unroll
        for (int kk = 0; kk < 16; ++kk) {
            ulonglong2 h0 = hp0[kk];
            ulonglong2 h1 = hp1[kk];
            ulonglong2 h2 = hp2[kk];
            ulonglong2 h3 = hp3[kk];
            u64 w0 = wp[2 * kk];
            u64 w1 = wp[2 * kk + 1];
            fma2(a0, h0.x, w0);
            fma2(a1, h1.x, w0);
            fma2(a2, h2.x, w0);
            fma2(a3, h3.x, w0);
            fma2(a0, h0.y, w1);
            fma2(a1, h1.y, w1);
            fma2(a2, h2.y, w1);
            fma2(a3, h3.y, w1);
        }
        float p0, p1, p2, p3, tl, th;
        upk2(a0, tl, th); p0 = tl + th;
        upk2(a1, tl, th); p1 = tl + th;
        upk2(a2, tl, th); p2 = tl + th;
        upk2(a3, tl, th); p3 = tl + th;

        // exchange: each side publishes the 2 partials the other side combines
        if (hi) partH[g] = make_float2(p0, p1);
        else    partL[g] = make_float2(p2, p3);
        __syncthreads();

        // -------- phase A: combine + gate nonlinearity, 2 rows/thread -----
        float2 o = hi ? partL[g] : partH[g];
        float ga = hi ? (o.x + p2 + bh) : (p0 + o.x + bh);   // row rowA
        float gb = hi ? (o.y + p3 + bh) : (p1 + o.y + bh);   // row rowA+1
        if (sec == 0) {
            rz[rowA    ][j].x = sig_ap(xva + ga);
            rz[rowA + 1][j].x = sig_ap(xvb + gb);
        } else if (sec == 1) {
            rz[rowA    ][j].y = sig_ap(xva + ga);
            rz[rowA + 1][j].y = sig_ap(xvb + gb);
        } else {
            gx[rowA    ][j] = make_float2(ga, xva);
            gx[rowA + 1][j] = make_float2(gb, xvb);
        }
        __syncthreads();

        // -------- phase B: tanh + blend, 512 elements / 768 threads -------
        if (rB < 4) {
            float2 rzv = rz[rB][cB];
            float2 gxv = gx[rB][cB];
            float  ho  = h_s[rB][cB];
            float  n   = tanh_ap(fmaf(rzv.x, gxv.x, gxv.y));
            float  h   = fmaf(rzv.y, ho - n, n);
            h_s[rB][cB] = h;
            if (WRITE_ALL) houtB[0] = h;
            else if (t == S_ - 1) g_h2last[(rb + rB) * H_ + cB] = h;
        }
        __syncthreads();
        if (WRITE_ALL) houtB += H_;
    }
}

// ============================================================================
// Phase 5: out[b][c] = h2last[b] . fc_w[c] + fc_b[c]
// ============================================================================
__global__ __launch_bounds__(128) void fc_kernel(
    const float* __restrict__ fw, const float* __restrict__ fb,
    float* __restrict__ out)
{
    __shared__ float sh[H_];
    const int b = blockIdx.x;
    sh[threadIdx.x] = g_h2last[b * H_ + threadIdx.x];
    __syncthreads();
    if (threadIdx.x < C_) {
        const int c = threadIdx.x;
        float acc = fb[c];
#pragma unroll
        for (int jj = 0; jj < H_; ++jj)
            acc += sh[jj] * fw[c * H_ + jj];
        out[b * C_ + c] = acc;
    }
}

extern "C" void kernel_launch(void* const* d_in, const int* in_sizes, int n_in,
                              void* d_out, int out_size)
{
    (void)in_sizes; (void)n_in; (void)out_size;
    const float* x      = (const float*)d_in[0];
    const float* W_ih0  = (const float*)d_in[1];
    const float* W_hh0  = (const float*)d_in[2];
    const float* b_ih0  = (const float*)d_in[3];
    const float* b_hh0  = (const float*)d_in[4];
    const float* W_ih1  = (const float*)d_in[5];
    const float* W_hh1  = (const float*)d_in[6];
    const float* b_ih1  = (const float*)d_in[7];
    const float* b_hh1  = (const float*)d_in[8];
    const float* fc_w   = (const float*)d_in[9];
    const float* fc_b   = (const float*)d_in[10];
    float* out = (float*)d_out;

    const int ntiles = (B_ * S_) / 64;   // 8192
    const int smem64  = 64  * 4 * (G_ + 64);   // 114688 B
    const int smem128 = 128 * 4 * (G_ + 64);   // 229376 B

    cudaFuncSetAttribute(gemm_xg_kernel<64, false>,
                         cudaFuncAttributeMaxDynamicSharedMemorySize, smem64);
    cudaFuncSetAttribute(gemm_xg_kernel<128, true>,
                         cudaFuncAttributeMaxDynamicSharedMemorySize, smem128);

    // Layer 0
    gemm_xg_kernel<64, false><<<148, 512, smem64>>>(x, W_ih0, b_ih0, ntiles);
    gru_rec_kernel<true><<<128, 768>>>(W_hh0, b_hh0);
    // Layer 1
    gemm_xg_kernel<128, true><<<148, 512, smem128>>>(nullptr, W_ih1, b_ih1, ntiles);
    gru_rec_kernel<false><<<128, 768>>>(W_hh1, b_hh1);
    // Head
    fc_kernel<<<B_, 128>>>(fc_w, fc_b, out);
}

// round 6
// speedup vs baseline: 1.1919x; 1.1919x over previous
#include <cuda_runtime.h>
#include <cstdint>
#include <cstddef>

// Problem dims
#define B_  512
#define S_  1024
#define I_  64
#define H_  128
#define G_  384   // 3*H
#define C_  10

// Scratch (device globals: allocation APIs are forbidden)
__device__ float g_xg[(size_t)B_ * S_ * G_];    // input-gate preactivations
__device__ float g_h1[(size_t)B_ * S_ * H_];    // layer0 hidden outputs
__device__ float g_h2last[B_ * H_];             // last hidden of layer1

typedef unsigned long long u64;

__device__ __forceinline__ u64 pk2(float lo, float hi) {
    u64 r; asm("mov.b64 %0, {%1, %2};" : "=l"(r) : "f"(lo), "f"(hi)); return r;
}
__device__ __forceinline__ void upk2(u64 v, float& lo, float& hi) {
    asm("mov.b64 {%0, %1}, %2;" : "=f"(lo), "=f"(hi) : "l"(v));
}
__device__ __forceinline__ void fma2(u64& d, u64 a, u64 b) {
    asm("fma.rn.f32x2 %0, %1, %2, %0;" : "+l"(d) : "l"(a), "l"(b));
}

// MUFU.TANH — single-op tanh (sm_75+), ~2^-11 rel err
__device__ __forceinline__ float tanh_ap(float x) {
    float y; asm("tanh.approx.f32 %0, %1;" : "=f"(y) : "f"(x)); return y;
}
__device__ __forceinline__ float sig_ap(float x) {
    return fmaf(tanh_ap(0.5f * x), 0.5f, 0.5f);
}

// ============================================================================
// Phase 1/3: xg[m][g] = sum_k A[m][k] * W[g][k] + bias[g]
// Persistent CTAs; W k-major in smem; 64-row M tiles; fp32x2 FMA; 256 threads.
// Next A tile prefetched into registers while computing the current one.
// ============================================================================
template<int K, bool A_IS_H1>
__global__ __launch_bounds__(256) void gemm_xg_kernel(
    const float* __restrict__ Ain, const float* __restrict__ W,
    const float* __restrict__ bias, int ntiles)
{
    extern __shared__ float smem[];
    float* Ws = smem;              // [K][384], k-major
    float* As = smem + K * G_;     // [64][K]
    const float* A = A_IS_H1 ? g_h1 : Ain;

    const int tid = threadIdx.x;
    constexpr int PF = (64 * K / 4) / 256;   // float4 per thread per tile

    for (int idx = tid; idx < G_ * (K / 4); idx += 256) {
        int kq = idx / G_;
        int g  = idx - kq * G_;
        float4 w4 = *reinterpret_cast<const float4*>(W + (size_t)g * K + 4 * kq);
        Ws[(4 * kq + 0) * G_ + g] = w4.x;
        Ws[(4 * kq + 1) * G_ + g] = w4.y;
        Ws[(4 * kq + 2) * G_ + g] = w4.z;
        Ws[(4 * kq + 3) * G_ + g] = w4.w;
    }

    const int cg = tid & 31;
    const int rg = tid >> 5;

    float4 bv[3];
#pragma unroll
    for (int gg = 0; gg < 3; ++gg)
        bv[gg] = *reinterpret_cast<const float4*>(bias + gg * H_ + 4 * cg);

    int tile = blockIdx.x;
    float4 pf[PF];
    if (tile < ntiles) {
        const float4* Ab = reinterpret_cast<const float4*>(A + (size_t)tile * 64 * K);
#pragma unroll
        for (int i = 0; i < PF; ++i) pf[i] = Ab[tid + 256 * i];
    }
    __syncthreads();

    for (; tile < ntiles; tile += gridDim.x) {
#pragma unroll
        for (int i = 0; i < PF; ++i)
            reinterpret_cast<float4*>(As)[tid + 256 * i] = pf[i];
        __syncthreads();

        int ntile = tile + gridDim.x;
        if (ntile < ntiles) {
            const float4* Ab = reinterpret_cast<const float4*>(A + (size_t)ntile * 64 * K);
#pragma unroll
            for (int i = 0; i < PF; ++i) pf[i] = Ab[tid + 256 * i];
        }

        u64 acc[8][3][2];
#pragma unroll
        for (int r = 0; r < 8; ++r)
#pragma unroll
            for (int gg = 0; gg < 3; ++gg) {
                acc[r][gg][0] = 0ull;
                acc[r][gg][1] = 0ull;
            }

#pragma unroll 2
        for (int k4 = 0; k4 < K; k4 += 4) {
            float4 af[8];
#pragma unroll
            for (int r = 0; r < 8; ++r)
                af[r] = *reinterpret_cast<const float4*>(&As[(rg * 8 + r) * K + k4]);
#pragma unroll
            for (int kk = 0; kk < 4; ++kk) {
                ulonglong2 wp[3];
#pragma unroll
                for (int gg = 0; gg < 3; ++gg)
                    wp[gg] = *reinterpret_cast<const ulonglong2*>(
                        &Ws[(size_t)(k4 + kk) * G_ + gg * H_ + 4 * cg]);
#pragma unroll
                for (int r = 0; r < 8; ++r) {
                    float a = (kk == 0) ? af[r].x : (kk == 1) ? af[r].y
                            : (kk == 2) ? af[r].z : af[r].w;
                    u64 ad = pk2(a, a);
#pragma unroll
                    for (int gg = 0; gg < 3; ++gg) {
                        fma2(acc[r][gg][0], ad, wp[gg].x);
                        fma2(acc[r][gg][1], ad, wp[gg].y);
                    }
                }
            }
        }

        float* Cb = g_xg + (size_t)tile * 64 * G_;
#pragma unroll
        for (int r = 0; r < 8; ++r) {
#pragma unroll
            for (int gg = 0; gg < 3; ++gg) {
                float x0, x1, x2, x3;
                upk2(acc[r][gg][0], x0, x1);
                upk2(acc[r][gg][1], x2, x3);
                float4 o = make_float4(x0 + bv[gg].x, x1 + bv[gg].y,
                                       x2 + bv[gg].z, x3 + bv[gg].w);
                *reinterpret_cast<float4*>(&Cb[(size_t)(rg * 8 + r) * G_ + gg * H_ + 4 * cg]) = o;
            }
        }
        __syncthreads();
    }
}

// ============================================================================
// Phase 2/4: recurrent scan. 128 CTAs x 4 batch rows, 384 threads.
// Thread g owns gate column g; W_hh column held as 64 packed u64 k-pairs in
// registers; fp32x2 pairing along k. h state [4 rows][128 k] planar in smem.
// 2 barriers/step; MUFU.TANH nonlinearities; compiler-scheduled dot.
// ============================================================================
template<bool WRITE_ALL>
__global__ __launch_bounds__(384, 1) void gru_rec_kernel(
    const float* __restrict__ Whh, const float* __restrict__ bhh)
{
    __shared__ float h_s[4][H_];
    __shared__ float4 rbuf[H_];
    __shared__ float4 zbuf[H_];

    const int g  = threadIdx.x;
    const int rb = blockIdx.x * 4;

    // W_hh row as 64 packed (w[2k], w[2k+1]) u64s — loop-invariant, registers
    u64 wp[64];
    const u64* wrow = reinterpret_cast<const u64*>(Whh + (size_t)g * H_);
#pragma unroll
    for (int kk = 0; kk < 64; ++kk) wp[kk] = wrow[kk];
    const float bh = bhh[g];

    for (int idx = g; idx < 4 * H_; idx += 384)
        (&h_s[0][0])[idx] = 0.f;
    __syncthreads();

    const int sec = g >> 7;
    const int j   = g & 127;

    const size_t rstride = (size_t)S_ * G_;
    const float* xp = g_xg + (size_t)rb * rstride + g;
    float* hall = g_h1 + ((size_t)rb * S_) * H_ + j;

    const ulonglong2* hr0 = reinterpret_cast<const ulonglong2*>(h_s[0]);
    const ulonglong2* hr1 = reinterpret_cast<const ulonglong2*>(h_s[1]);
    const ulonglong2* hr2 = reinterpret_cast<const ulonglong2*>(h_s[2]);
    const ulonglong2* hr3 = reinterpret_cast<const ulonglong2*>(h_s[3]);

    for (int t = 0; t < S_; ++t) {
        // xg loads for the 4 rows: issued now, consumed after the dot
        float xv0 = __ldg(xp);
        float xv1 = __ldg(xp + rstride);
        float xv2 = __ldg(xp + 2 * rstride);
        float xv3 = __ldg(xp + 3 * rstride);
        xp += G_;

        u64 a0 = 0ull, a1 = 0ull, a2 = 0ull, a3 = 0ull;
#pragma unroll
        for (int kk = 0; kk < 32; ++kk) {
            ulonglong2 h0 = hr0[kk];
            ulonglong2 h1 = hr1[kk];
            ulonglong2 h2 = hr2[kk];
            ulonglong2 h3 = hr3[kk];
            u64 w0 = wp[2 * kk];
            u64 w1 = wp[2 * kk + 1];
            fma2(a0, h0.x, w0);
            fma2(a1, h1.x, w0);
            fma2(a2, h2.x, w0);
            fma2(a3, h3.x, w0);
            fma2(a0, h0.y, w1);
            fma2(a1, h1.y, w1);
            fma2(a2, h2.y, w1);
            fma2(a3, h3.y, w1);
        }
        float g0, g1, g2, g3, tlo, thi;
        upk2(a0, tlo, thi); g0 = tlo + thi + bh;
        upk2(a1, tlo, thi); g1 = tlo + thi + bh;
        upk2(a2, tlo, thi); g2 = tlo + thi + bh;
        upk2(a3, tlo, thi); g3 = tlo + thi + bh;

        if (sec == 0) {
            rbuf[j] = make_float4(sig_ap(xv0 + g0), sig_ap(xv1 + g1),
                                  sig_ap(xv2 + g2), sig_ap(xv3 + g3));
        } else if (sec == 1) {
            zbuf[j] = make_float4(sig_ap(xv0 + g0), sig_ap(xv1 + g1),
                                  sig_ap(xv2 + g2), sig_ap(xv3 + g3));
        }
        __syncthreads();
        if (sec == 2) {
            float4 rr = rbuf[j];
            float4 zz = zbuf[j];
            float ho0 = h_s[0][j], ho1 = h_s[1][j], ho2 = h_s[2][j], ho3 = h_s[3][j];
            float n0 = tanh_ap(fmaf(rr.x, g0, xv0));
            float n1 = tanh_ap(fmaf(rr.y, g1, xv1));
            float n2 = tanh_ap(fmaf(rr.z, g2, xv2));
            float n3 = tanh_ap(fmaf(rr.w, g3, xv3));
            float h0 = fmaf(zz.x, ho0 - n0, n0);
            float h1 = fmaf(zz.y, ho1 - n1, n1);
            float h2 = fmaf(zz.z, ho2 - n2, n2);
            float h3 = fmaf(zz.w, ho3 - n3, n3);
            h_s[0][j] = h0;
            h_s[1][j] = h1;
            h_s[2][j] = h2;
            h_s[3][j] = h3;
            if (WRITE_ALL) {
                hall[0]                        = h0;
                hall[(size_t)S_ * H_]          = h1;
                hall[2 * (size_t)S_ * H_]      = h2;
                hall[3 * (size_t)S_ * H_]      = h3;
            } else if (t == S_ - 1) {
                g_h2last[(rb + 0) * H_ + j] = h0;
                g_h2last[(rb + 1) * H_ + j] = h1;
                g_h2last[(rb + 2) * H_ + j] = h2;
                g_h2last[(rb + 3) * H_ + j] = h3;
            }
        }
        __syncthreads();
        if (WRITE_ALL) hall += H_;
    }
}

// ============================================================================
// Phase 5: out[b][c] = h2last[b] . fc_w[c] + fc_b[c]
// ============================================================================
__global__ __launch_bounds__(128) void fc_kernel(
    const float* __restrict__ fw, const float* __restrict__ fb,
    float* __restrict__ out)
{
    __shared__ float sh[H_];
    const int b = blockIdx.x;
    sh[threadIdx.x] = g_h2last[b * H_ + threadIdx.x];
    __syncthreads();
    if (threadIdx.x < C_) {
        const int c = threadIdx.x;
        float acc = fb[c];
#pragma unroll
        for (int jj = 0; jj < H_; ++jj)
            acc += sh[jj] * fw[c * H_ + jj];
        out[b * C_ + c] = acc;
    }
}

extern "C" void kernel_launch(void* const* d_in, const int* in_sizes, int n_in,
                              void* d_out, int out_size)
{
    (void)in_sizes; (void)n_in; (void)out_size;
    const float* x      = (const float*)d_in[0];
    const float* W_ih0  = (const float*)d_in[1];
    const float* W_hh0  = (const float*)d_in[2];
    const float* b_ih0  = (const float*)d_in[3];
    const float* b_hh0  = (const float*)d_in[4];
    const float* W_ih1  = (const float*)d_in[5];
    const float* W_hh1  = (const float*)d_in[6];
    const float* b_ih1  = (const float*)d_in[7];
    const float* b_hh1  = (const float*)d_in[8];
    const float* fc_w   = (const float*)d_in[9];
    const float* fc_b   = (const float*)d_in[10];
    float* out = (float*)d_out;

    const int ntiles = (B_ * S_) / 64;   // 8192
    const int smem64  = 64  * 4 * (G_ + 64);   // 114688 B
    const int smem128 = 128 * 4 * (G_ + 64);   // 229376 B

    cudaFuncSetAttribute(gemm_xg_kernel<64, false>,
                         cudaFuncAttributeMaxDynamicSharedMemorySize, smem64);
    cudaFuncSetAttribute(gemm_xg_kernel<128, true>,
                         cudaFuncAttributeMaxDynamicSharedMemorySize, smem128);

    // Layer 0
    gemm_xg_kernel<64, false><<<148, 256, smem64>>>(x, W_ih0, b_ih0, ntiles);
    gru_rec_kernel<true><<<128, 384>>>(W_hh0, b_hh0);
    // Layer 1
    gemm_xg_kernel<128, true><<<148, 256, smem128>>>(nullptr, W_ih1, b_ih1, ntiles);
    gru_rec_kernel<false><<<128, 384>>>(W_hh1, b_hh1);
    // Head
    fc_kernel<<<B_, 128>>>(fc_w, fc_b, out);
}

// round 7
// speedup vs baseline: 1.3144x; 1.1028x over previous
#include <cuda_runtime.h>
#include <cstdint>
#include <cstddef>

// Problem dims
#define B_  512
#define S_  1024
#define I_  64
#define H_  128
#define G_  384   // 3*H
#define C_  10

// Scratch (device globals: allocation APIs are forbidden)
__device__ float g_xg[(size_t)B_ * S_ * G_];    // input-gate preactivations
__device__ float g_h1[(size_t)B_ * S_ * H_];    // layer0 hidden outputs
__device__ float g_h2last[B_ * H_];             // last hidden of layer1

typedef unsigned long long u64;

__device__ __forceinline__ u64 pk2(float lo, float hi) {
    u64 r; asm("mov.b64 %0, {%1, %2};" : "=l"(r) : "f"(lo), "f"(hi)); return r;
}
__device__ __forceinline__ void upk2(u64 v, float& lo, float& hi) {
    asm("mov.b64 {%0, %1}, %2;" : "=f"(lo), "=f"(hi) : "l"(v));
}
__device__ __forceinline__ void fma2(u64& d, u64 a, u64 b) {
    asm("fma.rn.f32x2 %0, %1, %2, %0;" : "+l"(d) : "l"(a), "l"(b));
}

// MUFU.TANH — single-op tanh (sm_75+), ~2^-11 rel err
__device__ __forceinline__ float tanh_ap(float x) {
    float y; asm("tanh.approx.f32 %0, %1;" : "=f"(y) : "f"(x)); return y;
}
__device__ __forceinline__ float sig_ap(float x) {
    return fmaf(tanh_ap(0.5f * x), 0.5f, 0.5f);
}

__device__ __forceinline__ uint32_t smem_u32(const void* p) {
    uint32_t a;
    asm("{ .reg .u64 t; cvta.to.shared.u64 t, %1; cvt.u32.u64 %0, t; }"
        : "=r"(a) : "l"(p));
    return a;
}
// Predicated 4-byte cp.async: issue point pinned by asm volatile + memory clobber
__device__ __forceinline__ void cp_async4(uint32_t dst, const float* src, int pred) {
    asm volatile(
        "{\n\t.reg .pred p;\n\tsetp.ne.u32 p, %2, 0;\n\t"
        "@p cp.async.ca.shared.global [%0], [%1], 4;\n\t}"
        :: "r"(dst), "l"(src), "r"(pred) : "memory");
}
__device__ __forceinline__ void cp_commit() {
    asm volatile("cp.async.commit_group;" ::: "memory");
}
__device__ __forceinline__ void cp_wait1() {
    asm volatile("cp.async.wait_group 1;" ::: "memory");
}

// ============================================================================
// Phase 1/3: xg[m][g] = sum_k A[m][k] * W[g][k] + bias[g]
// Persistent CTAs; W k-major in smem; 64-row M tiles; fp32x2 FMA; 256 threads.
// Next A tile prefetched into registers while computing the current one.
// ============================================================================
template<int K, bool A_IS_H1>
__global__ __launch_bounds__(256) void gemm_xg_kernel(
    const float* __restrict__ Ain, const float* __restrict__ W,
    const float* __restrict__ bias, int ntiles)
{
    extern __shared__ float smem[];
    float* Ws = smem;              // [K][384], k-major
    float* As = smem + K * G_;     // [64][K]
    const float* A = A_IS_H1 ? g_h1 : Ain;

    const int tid = threadIdx.x;
    constexpr int PF = (64 * K / 4) / 256;

    for (int idx = tid; idx < G_ * (K / 4); idx += 256) {
        int kq = idx / G_;
        int g  = idx - kq * G_;
        float4 w4 = *reinterpret_cast<const float4*>(W + (size_t)g * K + 4 * kq);
        Ws[(4 * kq + 0) * G_ + g] = w4.x;
        Ws[(4 * kq + 1) * G_ + g] = w4.y;
        Ws[(4 * kq + 2) * G_ + g] = w4.z;
        Ws[(4 * kq + 3) * G_ + g] = w4.w;
    }

    const int cg = tid & 31;
    const int rg = tid >> 5;

    float4 bv[3];
#pragma unroll
    for (int gg = 0; gg < 3; ++gg)
        bv[gg] = *reinterpret_cast<const float4*>(bias + gg * H_ + 4 * cg);

    int tile = blockIdx.x;
    float4 pf[PF];
    if (tile < ntiles) {
        const float4* Ab = reinterpret_cast<const float4*>(A + (size_t)tile * 64 * K);
#pragma unroll
        for (int i = 0; i < PF; ++i) pf[i] = Ab[tid + 256 * i];
    }
    __syncthreads();

    for (; tile < ntiles; tile += gridDim.x) {
#pragma unroll
        for (int i = 0; i < PF; ++i)
            reinterpret_cast<float4*>(As)[tid + 256 * i] = pf[i];
        __syncthreads();

        int ntile = tile + gridDim.x;
        if (ntile < ntiles) {
            const float4* Ab = reinterpret_cast<const float4*>(A + (size_t)ntile * 64 * K);
#pragma unroll
            for (int i = 0; i < PF; ++i) pf[i] = Ab[tid + 256 * i];
        }

        u64 acc[8][3][2];
#pragma unroll
        for (int r = 0; r < 8; ++r)
#pragma unroll
            for (int gg = 0; gg < 3; ++gg) {
                acc[r][gg][0] = 0ull;
                acc[r][gg][1] = 0ull;
            }

#pragma unroll 2
        for (int k4 = 0; k4 < K; k4 += 4) {
            float4 af[8];
#pragma unroll
            for (int r = 0; r < 8; ++r)
                af[r] = *reinterpret_cast<const float4*>(&As[(rg * 8 + r) * K + k4]);
#pragma unroll
            for (int kk = 0; kk < 4; ++kk) {
                ulonglong2 wp[3];
#pragma unroll
                for (int gg = 0; gg < 3; ++gg)
                    wp[gg] = *reinterpret_cast<const ulonglong2*>(
                        &Ws[(size_t)(k4 + kk) * G_ + gg * H_ + 4 * cg]);
#pragma unroll
                for (int r = 0; r < 8; ++r) {
                    float a = (kk == 0) ? af[r].x : (kk == 1) ? af[r].y
                            : (kk == 2) ? af[r].z : af[r].w;
                    u64 ad = pk2(a, a);
#pragma unroll
                    for (int gg = 0; gg < 3; ++gg) {
                        fma2(acc[r][gg][0], ad, wp[gg].x);
                        fma2(acc[r][gg][1], ad, wp[gg].y);
                    }
                }
            }
        }

        float* Cb = g_xg + (size_t)tile * 64 * G_;
#pragma unroll
        for (int r = 0; r < 8; ++r) {
#pragma unroll
            for (int gg = 0; gg < 3; ++gg) {
                float x0, x1, x2, x3;
                upk2(acc[r][gg][0], x0, x1);
                upk2(acc[r][gg][1], x2, x3);
                float4 o = make_float4(x0 + bv[gg].x, x1 + bv[gg].y,
                                       x2 + bv[gg].z, x3 + bv[gg].w);
                *reinterpret_cast<float4*>(&Cb[(size_t)(rg * 8 + r) * G_ + gg * H_ + 4 * cg]) = o;
            }
        }
        __syncthreads();
    }
}

// ============================================================================
// Phase 2/4: recurrent scan. 128 CTAs x 4 batch rows, 384 threads.
// Thread g owns gate column g; W_hh column as 64 packed u64 k-pairs in regs.
// xg is staged one timestep AHEAD through smem via cp.async (double buffer):
// the LDG issue point is pinned before the dot, so DRAM latency is covered by
// a full step (~2000+ cyc) instead of being exposed at the epilogue.
// Each thread reads back only its own staged bytes -> no barrier needed,
// cp.async.wait_group 1 suffices.
// ============================================================================
template<bool WRITE_ALL>
__global__ __launch_bounds__(384, 1) void gru_rec_kernel(
    const float* __restrict__ Whh, const float* __restrict__ bhh)
{
    __shared__ float h_s[4][H_];
    __shared__ float4 rbuf[H_];
    __shared__ float4 zbuf[H_];
    __shared__ float4 xstage[2][G_];   // [buf][gate] = 4 rows of xg per thread

    const int g  = threadIdx.x;
    const int rb = blockIdx.x * 4;

    // W_hh row as 64 packed (w[2k], w[2k+1]) u64s — loop-invariant, registers
    u64 wp[64];
    const u64* wrow = reinterpret_cast<const u64*>(Whh + (size_t)g * H_);
#pragma unroll
    for (int kk = 0; kk < 64; ++kk) wp[kk] = wrow[kk];
    const float bh = bhh[g];

    for (int idx = g; idx < 4 * H_; idx += 384)
        (&h_s[0][0])[idx] = 0.f;
    __syncthreads();

    const int sec = g >> 7;
    const int j   = g & 127;

    const size_t rstride = (size_t)S_ * G_;
    const float* xp = g_xg + (size_t)rb * rstride + g;   // next step to stage
    float* hall = g_h1 + ((size_t)rb * S_) * H_ + j;

    const uint32_t xs0 = smem_u32(&xstage[0][g]);
    const uint32_t xs1 = smem_u32(&xstage[1][g]);

    // Prologue: stage t=0 into buffer 0
    cp_async4(xs0 +  0, xp,               1);
    cp_async4(xs0 +  4, xp + rstride,     1);
    cp_async4(xs0 +  8, xp + 2 * rstride, 1);
    cp_async4(xs0 + 12, xp + 3 * rstride, 1);
    cp_commit();
    xp += G_;

    const ulonglong2* hr0 = reinterpret_cast<const ulonglong2*>(h_s[0]);
    const ulonglong2* hr1 = reinterpret_cast<const ulonglong2*>(h_s[1]);
    const ulonglong2* hr2 = reinterpret_cast<const ulonglong2*>(h_s[2]);
    const ulonglong2* hr3 = reinterpret_cast<const ulonglong2*>(h_s[3]);

    for (int t = 0; t < S_; ++t) {
        // Stage t+1 into the other buffer (issue pinned HERE, before the dot)
        {
            const uint32_t dst = (t & 1) ? xs0 : xs1;
            const int pred = (t + 1 < S_);
            cp_async4(dst +  0, xp,               pred);
            cp_async4(dst +  4, xp + rstride,     pred);
            cp_async4(dst +  8, xp + 2 * rstride, pred);
            cp_async4(dst + 12, xp + 3 * rstride, pred);
            cp_commit();
            xp += G_;
        }

        // -------- dot: h(t-1) . w for 4 rows --------
        u64 a0 = 0ull, a1 = 0ull, a2 = 0ull, a3 = 0ull;
#pragma unroll
        for (int kk = 0; kk < 32; ++kk) {
            ulonglong2 h0 = hr0[kk];
            ulonglong2 h1 = hr1[kk];
            ulonglong2 h2 = hr2[kk];
            ulonglong2 h3 = hr3[kk];
            u64 w0 = wp[2 * kk];
            u64 w1 = wp[2 * kk + 1];
            fma2(a0, h0.x, w0);
            fma2(a1, h1.x, w0);
            fma2(a2, h2.x, w0);
            fma2(a3, h3.x, w0);
            fma2(a0, h0.y, w1);
            fma2(a1, h1.y, w1);
            fma2(a2, h2.y, w1);
            fma2(a3, h3.y, w1);
        }
        float g0, g1, g2, g3, tlo, thi;
        upk2(a0, tlo, thi); g0 = tlo + thi + bh;
        upk2(a1, tlo, thi); g1 = tlo + thi + bh;
        upk2(a2, tlo, thi); g2 = tlo + thi + bh;
        upk2(a3, tlo, thi); g3 = tlo + thi + bh;

        // xg for THIS step: staged a full step ago, now local in smem
        cp_wait1();
        float4 xv = (t & 1) ? xstage[1][g] : xstage[0][g];

        if (sec == 0) {
            rbuf[j] = make_float4(sig_ap(xv.x + g0), sig_ap(xv.y + g1),
                                  sig_ap(xv.z + g2), sig_ap(xv.w + g3));
        } else if (sec == 1) {
            zbuf[j] = make_float4(sig_ap(xv.x + g0), sig_ap(xv.y + g1),
                                  sig_ap(xv.z + g2), sig_ap(xv.w + g3));
        }
        __syncthreads();
        if (sec == 2) {
            float4 rr = rbuf[j];
            float4 zz = zbuf[j];
            float ho0 = h_s[0][j], ho1 = h_s[1][j], ho2 = h_s[2][j], ho3 = h_s[3][j];
            float n0 = tanh_ap(fmaf(rr.x, g0, xv.x));
            float n1 = tanh_ap(fmaf(rr.y, g1, xv.y));
            float n2 = tanh_ap(fmaf(rr.z, g2, xv.z));
            float n3 = tanh_ap(fmaf(rr.w, g3, xv.w));
            float h0 = fmaf(zz.x, ho0 - n0, n0);
            float h1 = fmaf(zz.y, ho1 - n1, n1);
            float h2 = fmaf(zz.z, ho2 - n2, n2);
            float h3 = fmaf(zz.w, ho3 - n3, n3);
            h_s[0][j] = h0;
            h_s[1][j] = h1;
            h_s[2][j] = h2;
            h_s[3][j] = h3;
            if (WRITE_ALL) {
                hall[0]                        = h0;
                hall[(size_t)S_ * H_]          = h1;
                hall[2 * (size_t)S_ * H_]      = h2;
                hall[3 * (size_t)S_ * H_]      = h3;
            } else if (t == S_ - 1) {
                g_h2last[(rb + 0) * H_ + j] = h0;
                g_h2last[(rb + 1) * H_ + j] = h1;
                g_h2last[(rb + 2) * H_ + j] = h2;
                g_h2last[(rb + 3) * H_ + j] = h3;
            }
        }
        __syncthreads();
        if (WRITE_ALL) hall += H_;
    }
}

// ============================================================================
// Phase 5: out[b][c] = h2last[b] . fc_w[c] + fc_b[c]
// ============================================================================
__global__ __launch_bounds__(128) void fc_kernel(
    const float* __restrict__ fw, const float* __restrict__ fb,
    float* __restrict__ out)
{
    __shared__ float sh[H_];
    const int b = blockIdx.x;
    sh[threadIdx.x] = g_h2last[b * H_ + threadIdx.x];
    __syncthreads();
    if (threadIdx.x < C_) {
        const int c = threadIdx.x;
        float acc = fb[c];
#pragma unroll
        for (int jj = 0; jj < H_; ++jj)
            acc += sh[jj] * fw[c * H_ + jj];
        out[b * C_ + c] = acc;
    }
}

extern "C" void kernel_launch(void* const* d_in, const int* in_sizes, int n_in,
                              void* d_out, int out_size)
{
    (void)in_sizes; (void)n_in; (void)out_size;
    const float* x      = (const float*)d_in[0];
    const float* W_ih0  = (const float*)d_in[1];
    const float* W_hh0  = (const float*)d_in[2];
    const float* b_ih0  = (const float*)d_in[3];
    const float* b_hh0  = (const float*)d_in[4];
    const float* W_ih1  = (const float*)d_in[5];
    const float* W_hh1  = (const float*)d_in[6];
    const float* b_ih1  = (const float*)d_in[7];
    const float* b_hh1  = (const float*)d_in[8];
    const float* fc_w   = (const float*)d_in[9];
    const float* fc_b   = (const float*)d_in[10];
    float* out = (float*)d_out;

    const int ntiles = (B_ * S_) / 64;   // 8192
    const int smem64  = 64  * 4 * (G_ + 64);   // 114688 B
    const int smem128 = 128 * 4 * (G_ + 64);   // 229376 B

    cudaFuncSetAttribute(gemm_xg_kernel<64, false>,
                         cudaFuncAttributeMaxDynamicSharedMemorySize, smem64);
    cudaFuncSetAttribute(gemm_xg_kernel<128, true>,
                         cudaFuncAttributeMaxDynamicSharedMemorySize, smem128);

    // Layer 0
    gemm_xg_kernel<64, false><<<148, 256, smem64>>>(x, W_ih0, b_ih0, ntiles);
    gru_rec_kernel<true><<<128, 384>>>(W_hh0, b_hh0);
    // Layer 1
    gemm_xg_kernel<128, true><<<148, 256, smem128>>>(nullptr, W_ih1, b_ih1, ntiles);
    gru_rec_kernel<false><<<128, 384>>>(W_hh1, b_hh1);
    // Head
    fc_kernel<<<B_, 128>>>(fc_w, fc_b, out);
}